// round 2
// baseline (speedup 1.0000x reference)
#include <cuda_runtime.h>
#include <math.h>

// Problem constants
#define NN   4096
#define BB   4
#define DD   4
#define TT   5
#define F1C  32
#define F2C  64
#define CF   256            // BB * F2C  columns of cond matrix
#define JB   16             // rows of A per block in main kernel
#define TK   64             // k-tile size

// Scratch (device globals — no allocation allowed)
__device__ float g_cond[NN * CF];     // cond, layout [k][b*64+f]  (4 MB)
__device__ float g_invdeg[NN];
__device__ float g_alive[NN];

// packed fp32x2 FMA (Blackwell FFMA2 — reachable only via PTX)
__device__ __forceinline__ void fma2(float2 &a, const float2 &x, const float2 &y) {
    unsigned long long &ar = reinterpret_cast<unsigned long long &>(a);
    const unsigned long long &xr = reinterpret_cast<const unsigned long long &>(x);
    const unsigned long long &yr = reinterpret_cast<const unsigned long long &>(y);
    asm("fma.rn.f32x2 %0, %1, %2, %0;" : "+l"(ar) : "l"(xr), "l"(yr));
}

// ---------------------------------------------------------------------------
// Kernel 1: temporal conv  -> cond[n][b*64+f]
// grid 512 blocks x 128 threads; each block handles 32 (b,n) items,
// Wc1/Wc2 cached in shared once per block.
// ---------------------------------------------------------------------------
__global__ __launch_bounds__(128) void cond_kernel(
    const float* __restrict__ ts,
    const float* __restrict__ Wc1, const float* __restrict__ bc1,
    const float* __restrict__ Wc2, const float* __restrict__ bc2)
{
    __shared__ float sW2[3 * F1C * F2C];   // 24 KB
    __shared__ float sW1[3 * DD * F1C];    // 1.5 KB
    __shared__ float sb1[F1C];
    __shared__ float sb2[F2C];
    __shared__ float sx[TT][DD];
    __shared__ float sh[3][F1C];

    const int tid = threadIdx.x;
    for (int i = tid; i < 3 * F1C * F2C; i += 128) sW2[i] = Wc2[i];
    for (int i = tid; i < 3 * DD * F1C;  i += 128) sW1[i] = Wc1[i];
    if (tid < F1C) sb1[tid] = bc1[tid];
    if (tid < F2C) sb2[tid] = bc2[tid];
    __syncthreads();

    for (int it = 0; it < 32; it++) {
        const int item = blockIdx.x * 32 + it;       // 0..16383
        const int b = item >> 12;
        const int n = item & (NN - 1);

        if (tid < TT * DD) {
            int t = tid / DD, d = tid % DD;
            sx[t][d] = ts[((b * TT + t) * NN + n) * DD + d];
        }
        __syncthreads();

        if (tid < 3 * F1C) {
            int p = tid / F1C, c = tid % F1C;
            float s = sb1[c];
            #pragma unroll
            for (int r = 0; r < 3; r++)
                #pragma unroll
                for (int d = 0; d < DD; d++)
                    s += sx[p + r][d] * sW1[(r * DD + d) * F1C + c];
            sh[p][c] = fmaxf(s, 0.f);
        }
        __syncthreads();

        if (tid < F2C) {
            float s = sb2[tid];
            #pragma unroll
            for (int r = 0; r < 3; r++)
                for (int c = 0; c < F1C; c++)
                    s += sh[r][c] * sW2[(r * F1C + c) * F2C + tid];
            g_cond[n * CF + b * F2C + tid] = s;
        }
        __syncthreads();
    }
}

// ---------------------------------------------------------------------------
// Kernel 2: row degree -> 1/max(deg,1)
// ---------------------------------------------------------------------------
__global__ __launch_bounds__(256) void deg_kernel(const int* __restrict__ edges)
{
    const int j = blockIdx.x;
    const int tid = threadIdx.x;
    float s = 0.f;
    for (int k = tid; k < NN; k += 256) s += (float)edges[j * NN + k];
    __shared__ float red[256];
    red[tid] = s;
    __syncthreads();
    for (int off = 128; off > 0; off >>= 1) {
        if (tid < off) red[tid] += red[tid + off];
        __syncthreads();
    }
    if (tid == 0) g_invdeg[j] = 1.0f / fmaxf(red[0], 1.0f);
}

// ---------------------------------------------------------------------------
// Kernel 3: alive[k] = any(edges[:,k] != 0)
// ---------------------------------------------------------------------------
__global__ __launch_bounds__(256) void alive_kernel(const int* __restrict__ edges)
{
    const int k = blockIdx.x * blockDim.x + threadIdx.x;
    if (k >= NN) return;
    float a = 0.f;
    for (int j = 0; j < NN; j++) {
        if (edges[j * NN + k] != 0) { a = 1.f; break; }
    }
    g_alive[k] = a;
}

// ---------------------------------------------------------------------------
// Kernel 4: main — S = A @ cond via FFMA2, then fused per-row epilogue.
// grid 256 blocks x 256 threads; block = 16 A-rows x full 256 cond cols.
// dynamic smem: main phase  = cond tile (64x256 f32 = 64KB) + edge tile
//               (64 x 16 duplicated-f32x2 = 8KB)   -> 72 KB
//               epilogue    = S(16KB) Wg1(16KB) Wd(32KB) + small  -> <72 KB
// ---------------------------------------------------------------------------
#define SMEM_BYTES 73728

__global__ __launch_bounds__(256, 2) void main_kernel(
    const int*   __restrict__ edges,
    const float* __restrict__ ts,
    const float* __restrict__ Wg1, const float* __restrict__ bg,
    const float* __restrict__ Wd,  const float* __restrict__ bd,
    const float* __restrict__ Wo,  const float* __restrict__ bo,
    float* __restrict__ out)
{
    extern __shared__ char smem[];
    float*  sC = (float*)smem;                      // TK * CF floats
    float2* sE = (float2*)(smem + TK * CF * 4);     // TK * JB float2 (dup pairs)

    const int tid = threadIdx.x;
    const int j0  = blockIdx.x * JB;
    const int q   = tid >> 6;            // 0..3 : handles rows 4q..4q+3
    const int c4  = (tid & 63) * 4;      // column base (4 cols per thread)

    float2 acc[4][2];
    #pragma unroll
    for (int r = 0; r < 4; r++) {
        acc[r][0] = make_float2(0.f, 0.f);
        acc[r][1] = make_float2(0.f, 0.f);
    }

    for (int kt = 0; kt < NN / TK; kt++) {
        __syncthreads();
        // load cond tile (coalesced float4)
        {
            const float4* gsrc = (const float4*)(g_cond + kt * TK * CF);
            float4* dst = (float4*)sC;
            #pragma unroll
            for (int i = tid; i < TK * CF / 4; i += 256) dst[i] = gsrc[i];
        }
        // load edge tile -> duplicated float2 in k-major layout
        #pragma unroll
        for (int i = tid; i < JB * TK; i += 256) {
            int jj = i >> 6;          // 0..15
            int kc = i & 63;          // 0..63
            float e = (float)edges[(j0 + jj) * NN + kt * TK + kc];
            sE[kc * JB + jj] = make_float2(e, e);
        }
        __syncthreads();

        #pragma unroll 4
        for (int k = 0; k < TK; k++) {
            float4 v = *(const float4*)(sC + k * CF + c4);
            float2 v0 = make_float2(v.x, v.y);
            float2 v1 = make_float2(v.z, v.w);
            const float4* ep4 = (const float4*)(sE + k * JB + q * 4);
            float4 e01 = ep4[0];            // rows 4q, 4q+1 (dup pairs)
            float4 e23 = ep4[1];            // rows 4q+2, 4q+3
            float2 e0 = make_float2(e01.x, e01.y);
            float2 e1 = make_float2(e01.z, e01.w);
            float2 e2 = make_float2(e23.x, e23.y);
            float2 e3 = make_float2(e23.z, e23.w);
            fma2(acc[0][0], e0, v0);  fma2(acc[0][1], e0, v1);
            fma2(acc[1][0], e1, v0);  fma2(acc[1][1], e1, v1);
            fma2(acc[2][0], e2, v0);  fma2(acc[2][1], e2, v1);
            fma2(acc[3][0], e3, v0);  fma2(acc[3][1], e3, v1);
        }
    }
    __syncthreads();

    // ---- epilogue: spill S to smem, load weights, per-row tiny GEMVs ----
    float* S     = (float*)smem;                         // 16 x 256  (16 KB)
    float* sWg1  = (float*)(smem + 16384);               // 4096 f    (16 KB)
    float* sWd   = (float*)(smem + 32768);               // 8192 f    (32 KB)
    float* sWo   = (float*)(smem + 65536);               // 256 f
    float* sbg   = (float*)(smem + 65536 + 1024);        // 64
    float* sbd   = (float*)(smem + 65536 + 1024 + 256);  // 64
    float* sbo   = (float*)(smem + 65536 + 1024 + 512);  // 4 (pad 64)
    float* sagg  = (float*)(smem + 65536 + 2048);        // 256
    float* sG    = (float*)(smem + 65536 + 3072);        // 256
    float* sH    = (float*)(smem + 65536 + 4096);        // 256
    float* scond = (float*)(smem + 65536 + 5120);        // 256

    #pragma unroll
    for (int r = 0; r < 4; r++) {
        int jj = q * 4 + r;
        S[jj * CF + c4 + 0] = acc[r][0].x;
        S[jj * CF + c4 + 1] = acc[r][0].y;
        S[jj * CF + c4 + 2] = acc[r][1].x;
        S[jj * CF + c4 + 3] = acc[r][1].y;
    }
    for (int i = tid; i < 4096; i += 256) sWg1[i] = Wg1[i];
    for (int i = tid; i < 8192; i += 256) sWd[i]  = Wd[i];
    sWo[tid] = Wo[tid];                      // 64*4 = 256 elements
    if (tid < 64) { sbg[tid] = bg[tid]; sbd[tid] = bd[tid]; }
    if (tid < 4)  sbo[tid] = bo[tid];
    __syncthreads();

    const int b = tid >> 6;
    const int f = tid & 63;

    for (int jj = 0; jj < JB; jj++) {
        const int j = j0 + jj;
        const float invd  = g_invdeg[j];
        const float ediag = (float)edges[j * NN + j];
        const float aliv  = g_alive[j];

        const float cj = g_cond[j * CF + tid];     // tid == b*64+f
        scond[tid] = cj;
        sagg[tid] = (S[jj * CF + tid] - ediag * cj) * invd;
        __syncthreads();

        // G = tanh(agg @ Wg1 + bg) * alive
        float g = sbg[f];
        #pragma unroll
        for (int i = 0; i < 64; i++) g += sagg[b * 64 + i] * sWg1[i * 64 + f];
        sG[tid] = tanhf(g) * aliv;
        __syncthreads();

        // h = relu([cond, G] @ Wd + bd)
        float h = sbd[f];
        #pragma unroll
        for (int i = 0; i < 64; i++) h += scond[b * 64 + i] * sWd[i * 64 + f];
        #pragma unroll
        for (int i = 0; i < 64; i++) h += sG[b * 64 + i] * sWd[(64 + i) * 64 + f];
        sH[tid] = fmaxf(h, 0.f);
        __syncthreads();

        // out = last + tanh(h @ Wo + bo)
        if (tid < BB * DD) {
            int ob = tid >> 2, od = tid & 3;
            float o = sbo[od];
            #pragma unroll
            for (int i = 0; i < 64; i++) o += sH[ob * 64 + i] * sWo[i * DD + od];
            float last = ts[((ob * TT + 4) * NN + j) * DD + od];
            out[(ob * NN + j) * DD + od] = last + tanhf(o);
        }
        __syncthreads();
    }
}

// ---------------------------------------------------------------------------
// Inputs (metadata order): time_segs, edges, Wc1, bc1, Wc2, bc2,
//                          Wg1, bg, Wd, bd, Wo, bo
// ---------------------------------------------------------------------------
extern "C" void kernel_launch(void* const* d_in, const int* in_sizes, int n_in,
                              void* d_out, int out_size)
{
    const float* ts   = (const float*)d_in[0];
    const int*   edges= (const int*)  d_in[1];
    const float* Wc1  = (const float*)d_in[2];
    const float* bc1  = (const float*)d_in[3];
    const float* Wc2  = (const float*)d_in[4];
    const float* bc2  = (const float*)d_in[5];
    const float* Wg1  = (const float*)d_in[6];
    const float* bg   = (const float*)d_in[7];
    const float* Wd   = (const float*)d_in[8];
    const float* bd   = (const float*)d_in[9];
    const float* Wo   = (const float*)d_in[10];
    const float* bo   = (const float*)d_in[11];
    float* out = (float*)d_out;

    cudaFuncSetAttribute(main_kernel,
                         cudaFuncAttributeMaxDynamicSharedMemorySize, SMEM_BYTES);

    cond_kernel<<<512, 128>>>(ts, Wc1, bc1, Wc2, bc2);
    deg_kernel<<<NN, 256>>>(edges);
    alive_kernel<<<16, 256>>>(edges);
    main_kernel<<<NN / JB, 256, SMEM_BYTES>>>(edges, ts, Wg1, bg, Wd, bd,
                                              Wo, bo, out);
}

// round 3
// speedup vs baseline: 2.7627x; 2.7627x over previous
#include <cuda_runtime.h>
#include <cuda_bf16.h>
#include <math.h>
#include <stdint.h>

// Problem constants
#define NN   4096
#define BB   4
#define DD   4
#define TT   5
#define F1C  32
#define F2C  64
#define CF   256            // BB * F2C  columns of cond matrix

// GEMM tiling
#define MT   32             // rows per CTA
#define KT   64             // k tile
#define NKT  (NN / KT)      // 64 tiles
#define LDS_B 144           // padded smem row stride in bytes (72 bf16)
#define A_BYTES (MT * LDS_B)          // 4608
#define B_BYTES (CF * LDS_B)          // 36864
#define BUF_BYTES (A_BYTES + B_BYTES) // 41472
#define GEMM_SMEM (2 * BUF_BYTES)     // 82944

// Scratch (device globals — no allocation allowed)
__device__ float          g_cond[NN * CF];      // cond fp32, [n][b*64+f] (4 MB)
__device__ __nv_bfloat16  g_condT[CF * NN];     // cond bf16 transposed [c][n] (2 MB)
__device__ float          g_S[NN * CF];         // A @ cond result (4 MB)
__device__ float          g_invdeg[NN];
__device__ float          g_alive[NN];

// ---------------------------------------------------------------------------
// cp.async helpers
// ---------------------------------------------------------------------------
__device__ __forceinline__ void cp_async16(void* smem_dst, const void* gmem_src) {
    unsigned saddr = (unsigned)__cvta_generic_to_shared(smem_dst);
    asm volatile("cp.async.cg.shared.global [%0], [%1], 16;\n"
                 :: "r"(saddr), "l"(gmem_src) : "memory");
}
__device__ __forceinline__ void cp_async_commit() {
    asm volatile("cp.async.commit_group;\n" ::: "memory");
}
__device__ __forceinline__ void cp_async_wait0() {
    asm volatile("cp.async.wait_group 0;\n" ::: "memory");
}

__device__ __forceinline__ void mma_bf16(float c[4],
    uint32_t a0, uint32_t a1, uint32_t a2, uint32_t a3,
    uint32_t b0, uint32_t b1)
{
    asm volatile(
        "mma.sync.aligned.m16n8k16.row.col.f32.bf16.bf16.f32 "
        "{%0,%1,%2,%3}, {%4,%5,%6,%7}, {%8,%9}, {%0,%1,%2,%3};\n"
        : "+f"(c[0]), "+f"(c[1]), "+f"(c[2]), "+f"(c[3])
        : "r"(a0), "r"(a1), "r"(a2), "r"(a3), "r"(b0), "r"(b1));
}

// ---------------------------------------------------------------------------
// Kernel 1: temporal conv  -> cond[n][b*64+f]  (fp32) + condT[c][n] (bf16)
// ---------------------------------------------------------------------------
__global__ __launch_bounds__(128) void cond_kernel(
    const float* __restrict__ ts,
    const float* __restrict__ Wc1, const float* __restrict__ bc1,
    const float* __restrict__ Wc2, const float* __restrict__ bc2)
{
    __shared__ float sW2[3 * F1C * F2C];   // 24 KB
    __shared__ float sW1[3 * DD * F1C];    // 1.5 KB
    __shared__ float sb1[F1C];
    __shared__ float sb2[F2C];
    __shared__ float sx[TT][DD];
    __shared__ float sh[3][F1C];

    const int tid = threadIdx.x;
    for (int i = tid; i < 3 * F1C * F2C; i += 128) sW2[i] = Wc2[i];
    for (int i = tid; i < 3 * DD * F1C;  i += 128) sW1[i] = Wc1[i];
    if (tid < F1C) sb1[tid] = bc1[tid];
    if (tid < F2C) sb2[tid] = bc2[tid];
    __syncthreads();

    for (int it = 0; it < 32; it++) {
        const int item = blockIdx.x * 32 + it;       // 0..16383
        const int b = item >> 12;
        const int n = item & (NN - 1);

        if (tid < TT * DD) {
            int t = tid / DD, d = tid % DD;
            sx[t][d] = ts[((b * TT + t) * NN + n) * DD + d];
        }
        __syncthreads();

        if (tid < 3 * F1C) {
            int p = tid / F1C, c = tid % F1C;
            float s = sb1[c];
            #pragma unroll
            for (int r = 0; r < 3; r++)
                #pragma unroll
                for (int d = 0; d < DD; d++)
                    s += sx[p + r][d] * sW1[(r * DD + d) * F1C + c];
            sh[p][c] = fmaxf(s, 0.f);
        }
        __syncthreads();

        if (tid < F2C) {
            float s = sb2[tid];
            #pragma unroll
            for (int r = 0; r < 3; r++)
                for (int c = 0; c < F1C; c++)
                    s += sh[r][c] * sW2[(r * F1C + c) * F2C + tid];
            const int col = b * F2C + tid;
            g_cond[n * CF + col] = s;
            g_condT[col * NN + n] = __float2bfloat16(s);
        }
        __syncthreads();
    }
}

// ---------------------------------------------------------------------------
// Kernel 2: row degree -> 1/max(deg,1)
// ---------------------------------------------------------------------------
__global__ __launch_bounds__(256) void deg_kernel(const int* __restrict__ edges)
{
    const int j = blockIdx.x;
    const int tid = threadIdx.x;
    float s = 0.f;
    for (int k = tid; k < NN; k += 256) s += (float)edges[j * NN + k];
    __shared__ float red[256];
    red[tid] = s;
    __syncthreads();
    for (int off = 128; off > 0; off >>= 1) {
        if (tid < off) red[tid] += red[tid + off];
        __syncthreads();
    }
    if (tid == 0) g_invdeg[j] = 1.0f / fmaxf(red[0], 1.0f);
}

// ---------------------------------------------------------------------------
// Kernel 3: alive[k] = any(edges[:,k] != 0)   (coalesced across threads)
// ---------------------------------------------------------------------------
__global__ __launch_bounds__(256) void alive_kernel(const int* __restrict__ edges)
{
    const int k = blockIdx.x * blockDim.x + threadIdx.x;
    if (k >= NN) return;
    float a = 0.f;
    for (int j = 0; j < NN; j++) {
        if (edges[j * NN + k] != 0) { a = 1.f; break; }
    }
    g_alive[k] = a;
}

// ---------------------------------------------------------------------------
// Kernel 4: S = A @ cond  via bf16 mma.sync (tensor cores), fp32 accumulate.
// grid 128 CTAs x 256 threads. CTA = 32 rows x 256 cols, K-loop 4096.
// Warp w: cols [w*32, w*32+32), both 16-row m-tiles.
// smem: double-buffered  A tile 32x64 bf16 (stride 72) + B tile 256x64 bf16.
// ---------------------------------------------------------------------------
__global__ __launch_bounds__(256) void gemm_kernel(const int* __restrict__ edges)
{
    extern __shared__ char smem[];
    const int tid  = threadIdx.x;
    const int wid  = tid >> 5;
    const int lane = tid & 31;
    const int g    = lane >> 2;     // 0..7
    const int t    = lane & 3;      // 0..3
    const int n0   = wid * 32;
    const int j0   = blockIdx.x * MT;

    float acc[2][4][4];
    #pragma unroll
    for (int mi = 0; mi < 2; mi++)
        #pragma unroll
        for (int ni = 0; ni < 4; ni++)
            #pragma unroll
            for (int q = 0; q < 4; q++) acc[mi][ni][q] = 0.f;

    // A-staging indices: 512 int4 per tile, 2 per thread
    const int aidx  = tid * 2;            // even int4 index
    const int arow  = aidx >> 4;          // 0..31
    const int acol4 = aidx & 15;          // 0..14 (even)

    // ---- prologue: stage tile 0 into buffer 0 ----
    {
        char* Bs = smem + A_BYTES;
        for (int ch = tid; ch < CF * 8; ch += 256) {
            int row = ch >> 3, off = ch & 7;
            cp_async16(Bs + row * LDS_B + off * 16,
                       g_condT + row * NN + off * 8);
        }
        cp_async_commit();
        const int4* ep = (const int4*)(edges + (j0 + arow) * NN + acol4 * 4);
        int4 e0 = ep[0], e1 = ep[1];
        uint32_t w0 = (e0.x ? 0x3F80u : 0u) | ((e0.y ? 0x3F80u : 0u) << 16);
        uint32_t w1 = (e0.z ? 0x3F80u : 0u) | ((e0.w ? 0x3F80u : 0u) << 16);
        uint32_t w2 = (e1.x ? 0x3F80u : 0u) | ((e1.y ? 0x3F80u : 0u) << 16);
        uint32_t w3 = (e1.z ? 0x3F80u : 0u) | ((e1.w ? 0x3F80u : 0u) << 16);
        *(uint2*)(smem + arow * LDS_B + acol4 * 8)     = make_uint2(w0, w1);
        *(uint2*)(smem + arow * LDS_B + acol4 * 8 + 8) = make_uint2(w2, w3);
        cp_async_wait0();
        __syncthreads();
    }

    for (int kt = 0; kt < NKT; kt++) {
        char* Acur = smem + (kt & 1) * BUF_BYTES;
        char* Bcur = Acur + A_BYTES;
        char* Anxt = smem + ((kt + 1) & 1) * BUF_BYTES;
        char* Bnxt = Anxt + A_BYTES;

        int4 e0, e1;
        const bool pf = (kt + 1 < NKT);
        if (pf) {
            const int knext = (kt + 1) * KT;
            for (int ch = tid; ch < CF * 8; ch += 256) {
                int row = ch >> 3, off = ch & 7;
                cp_async16(Bnxt + row * LDS_B + off * 16,
                           g_condT + row * NN + knext + off * 8);
            }
            cp_async_commit();
            const int4* ep = (const int4*)(edges + (j0 + arow) * NN + knext + acol4 * 4);
            e0 = ep[0]; e1 = ep[1];
        }

        // ---- compute 4 k16 steps on current buffers ----
        #pragma unroll
        for (int kk = 0; kk < 4; kk++) {
            const int kb = kk * 32 + t * 4;   // byte offset along k
            uint32_t a0 = *(const uint32_t*)(Acur + (g)      * LDS_B + kb);
            uint32_t a1 = *(const uint32_t*)(Acur + (g + 8)  * LDS_B + kb);
            uint32_t a2 = *(const uint32_t*)(Acur + (g)      * LDS_B + kb + 16);
            uint32_t a3 = *(const uint32_t*)(Acur + (g + 8)  * LDS_B + kb + 16);
            uint32_t a4 = *(const uint32_t*)(Acur + (16 + g)     * LDS_B + kb);
            uint32_t a5 = *(const uint32_t*)(Acur + (16 + g + 8) * LDS_B + kb);
            uint32_t a6 = *(const uint32_t*)(Acur + (16 + g)     * LDS_B + kb + 16);
            uint32_t a7 = *(const uint32_t*)(Acur + (16 + g + 8) * LDS_B + kb + 16);
            #pragma unroll
            for (int ni = 0; ni < 4; ni++) {
                const char* Bb = Bcur + (n0 + ni * 8 + g) * LDS_B + kb;
                uint32_t b0 = *(const uint32_t*)(Bb);
                uint32_t b1 = *(const uint32_t*)(Bb + 16);
                mma_bf16(acc[0][ni], a0, a1, a2, a3, b0, b1);
                mma_bf16(acc[1][ni], a4, a5, a6, a7, b0, b1);
            }
        }

        if (pf) {
            uint32_t w0 = (e0.x ? 0x3F80u : 0u) | ((e0.y ? 0x3F80u : 0u) << 16);
            uint32_t w1 = (e0.z ? 0x3F80u : 0u) | ((e0.w ? 0x3F80u : 0u) << 16);
            uint32_t w2 = (e1.x ? 0x3F80u : 0u) | ((e1.y ? 0x3F80u : 0u) << 16);
            uint32_t w3 = (e1.z ? 0x3F80u : 0u) | ((e1.w ? 0x3F80u : 0u) << 16);
            *(uint2*)(Anxt + arow * LDS_B + acol4 * 8)     = make_uint2(w0, w1);
            *(uint2*)(Anxt + arow * LDS_B + acol4 * 8 + 8) = make_uint2(w2, w3);
        }
        cp_async_wait0();
        __syncthreads();
    }

    // ---- store S ----
    #pragma unroll
    for (int mi = 0; mi < 2; mi++) {
        const int row = j0 + mi * 16 + g;
        #pragma unroll
        for (int ni = 0; ni < 4; ni++) {
            const int col = n0 + ni * 8 + 2 * t;
            *(float2*)&g_S[row * CF + col]       = make_float2(acc[mi][ni][0], acc[mi][ni][1]);
            *(float2*)&g_S[(row + 8) * CF + col] = make_float2(acc[mi][ni][2], acc[mi][ni][3]);
        }
    }
}

// ---------------------------------------------------------------------------
// Kernel 5: epilogue — per-row tiny GEMVs
// grid 256 blocks x 256 threads; block = 16 rows. Dynamic smem ~55 KB.
// ---------------------------------------------------------------------------
#define EPI_SMEM (13760 * 4)

__global__ __launch_bounds__(256) void epi_kernel(
    const int*   __restrict__ edges,
    const float* __restrict__ ts,
    const float* __restrict__ Wg1, const float* __restrict__ bg,
    const float* __restrict__ Wd,  const float* __restrict__ bd,
    const float* __restrict__ Wo,  const float* __restrict__ bo,
    float* __restrict__ out)
{
    extern __shared__ float sm[];
    float* sWg1  = sm;             // 4096
    float* sWd   = sm + 4096;      // 8192
    float* sWo   = sm + 12288;     // 256
    float* sbg   = sm + 12544;     // 64
    float* sbd   = sm + 12608;     // 64
    float* sbo   = sm + 12672;     // 64 (4 used)
    float* sagg  = sm + 12736;     // 256
    float* sG    = sm + 12992;     // 256
    float* sH    = sm + 13248;     // 256
    float* scond = sm + 13504;     // 256

    const int tid = threadIdx.x;
    const int j0  = blockIdx.x * 16;

    for (int i = tid; i < 4096; i += 256) sWg1[i] = Wg1[i];
    for (int i = tid; i < 8192; i += 256) sWd[i]  = Wd[i];
    sWo[tid] = Wo[tid];
    if (tid < 64) { sbg[tid] = bg[tid]; sbd[tid] = bd[tid]; }
    if (tid < 4)  sbo[tid] = bo[tid];
    __syncthreads();

    const int b = tid >> 6;
    const int f = tid & 63;

    for (int jj = 0; jj < 16; jj++) {
        const int j = j0 + jj;
        const float invd  = g_invdeg[j];
        const float ediag = (float)edges[j * NN + j];
        const float aliv  = g_alive[j];

        const float cj = g_cond[j * CF + tid];
        scond[tid] = cj;
        sagg[tid]  = (g_S[j * CF + tid] - ediag * cj) * invd;
        __syncthreads();

        // G = tanh(agg @ Wg1 + bg) * alive
        float gv = sbg[f];
        #pragma unroll
        for (int i = 0; i < 64; i++) gv += sagg[b * 64 + i] * sWg1[i * 64 + f];
        sG[tid] = tanhf(gv) * aliv;
        __syncthreads();

        // h = relu([cond, G] @ Wd + bd)
        float h = sbd[f];
        #pragma unroll
        for (int i = 0; i < 64; i++) h += scond[b * 64 + i] * sWd[i * 64 + f];
        #pragma unroll
        for (int i = 0; i < 64; i++) h += sG[b * 64 + i] * sWd[(64 + i) * 64 + f];
        sH[tid] = fmaxf(h, 0.f);
        __syncthreads();

        // out = last + tanh(h @ Wo + bo)
        if (tid < BB * DD) {
            int ob = tid >> 2, od = tid & 3;
            float o = sbo[od];
            #pragma unroll
            for (int i = 0; i < 64; i++) o += sH[ob * 64 + i] * sWo[i * DD + od];
            float last = ts[((ob * TT + 4) * NN + j) * DD + od];
            out[(ob * NN + j) * DD + od] = last + tanhf(o);
        }
        __syncthreads();
    }
}

// ---------------------------------------------------------------------------
// Inputs (metadata order): time_segs, edges, Wc1, bc1, Wc2, bc2,
//                          Wg1, bg, Wd, bd, Wo, bo
// ---------------------------------------------------------------------------
extern "C" void kernel_launch(void* const* d_in, const int* in_sizes, int n_in,
                              void* d_out, int out_size)
{
    const float* ts   = (const float*)d_in[0];
    const int*   edges= (const int*)  d_in[1];
    const float* Wc1  = (const float*)d_in[2];
    const float* bc1  = (const float*)d_in[3];
    const float* Wc2  = (const float*)d_in[4];
    const float* bc2  = (const float*)d_in[5];
    const float* Wg1  = (const float*)d_in[6];
    const float* bg   = (const float*)d_in[7];
    const float* Wd   = (const float*)d_in[8];
    const float* bd   = (const float*)d_in[9];
    const float* Wo   = (const float*)d_in[10];
    const float* bo   = (const float*)d_in[11];
    float* out = (float*)d_out;

    static bool attr_done = false;
    if (!attr_done) {
        cudaFuncSetAttribute(gemm_kernel,
                             cudaFuncAttributeMaxDynamicSharedMemorySize, GEMM_SMEM);
        cudaFuncSetAttribute(epi_kernel,
                             cudaFuncAttributeMaxDynamicSharedMemorySize, EPI_SMEM);
        attr_done = true;
    }

    deg_kernel  <<<NN, 256>>>(edges);
    alive_kernel<<<16, 256>>>(edges);
    cond_kernel <<<512, 128>>>(ts, Wc1, bc1, Wc2, bc2);
    gemm_kernel <<<NN / MT, 256, GEMM_SMEM>>>(edges);
    epi_kernel  <<<NN / 16, 256, EPI_SMEM>>>(edges, ts, Wg1, bg, Wd, bd,
                                             Wo, bo, out);
}

// round 4
// speedup vs baseline: 3.3271x; 1.2043x over previous
#include <cuda_runtime.h>
#include <cuda_bf16.h>
#include <math.h>
#include <stdint.h>

// Problem constants
#define NN   4096
#define BB   4
#define DD   4
#define TT   5
#define F1C  32
#define F2C  64
#define CF   256            // BB * F2C columns of cond matrix

// GEMM tiling
#define MT   64             // rows per CTA
#define NT   128            // cols per CTA (== 2 batches)
#define KT   64             // k tile
#define NKT  (NN / KT)      // 64
#define LDSB 144            // padded smem row stride bytes (64 bf16 + pad)
#define BTILE (NT * LDSB)   // 18432
#define ATILE (MT * LDSB)   // 9216
#define MAIN_SMEM (3 * BTILE + 2 * ATILE)   // 73728
#define GEMM_SMEM 100352    // epilogue overlay (25088 floats)

// Scratch (device globals — no allocation allowed)
__device__ float          g_cond[NN * CF];      // cond fp32, [n][b*64+f]
__device__ __nv_bfloat16  g_condT[CF * NN];     // cond bf16 transposed [c][n]
__device__ float          g_alive[NN];

// ---------------------------------------------------------------------------
// helpers
// ---------------------------------------------------------------------------
__device__ __forceinline__ void cp_async16(void* smem_dst, const void* gmem_src) {
    unsigned saddr = (unsigned)__cvta_generic_to_shared(smem_dst);
    asm volatile("cp.async.cg.shared.global [%0], [%1], 16;\n"
                 :: "r"(saddr), "l"(gmem_src) : "memory");
}
__device__ __forceinline__ void cp_async_commit() {
    asm volatile("cp.async.commit_group;\n" ::: "memory");
}
template <int N>
__device__ __forceinline__ void cp_async_wait() {
    asm volatile("cp.async.wait_group %0;\n" :: "n"(N) : "memory");
}

__device__ __forceinline__ void mma_bf16(float c[4],
    uint32_t a0, uint32_t a1, uint32_t a2, uint32_t a3,
    uint32_t b0, uint32_t b1)
{
    asm volatile(
        "mma.sync.aligned.m16n8k16.row.col.f32.bf16.bf16.f32 "
        "{%0,%1,%2,%3}, {%4,%5,%6,%7}, {%8,%9}, {%0,%1,%2,%3};\n"
        : "+f"(c[0]), "+f"(c[1]), "+f"(c[2]), "+f"(c[3])
        : "r"(a0), "r"(a1), "r"(a2), "r"(a3), "r"(b0), "r"(b1));
}

// ---------------------------------------------------------------------------
// Kernel 1: temporal conv (warp-synchronous) -> g_cond fp32 + g_condT bf16
// grid 256 CTAs x 256 threads; CTA covers 16 consecutive n x all 4 b = 64
// items, 8 per warp. condT stored via smem transpose (coalesced).
// ---------------------------------------------------------------------------
__global__ __launch_bounds__(256) void cond_kernel(
    const float* __restrict__ ts,
    const float* __restrict__ Wc1, const float* __restrict__ bc1,
    const float* __restrict__ Wc2, const float* __restrict__ bc2)
{
    __shared__ float sW1[3 * DD * F1C];    // 384
    __shared__ float sW2[3 * F1C * F2C];   // 6144
    __shared__ float sb1[F1C];
    __shared__ float sb2[F2C];
    __shared__ float sx[8][20];
    __shared__ float sh[8][96];
    __shared__ __nv_bfloat16 scT[CF][16];  // 8 KB

    const int tid  = threadIdx.x;
    const int wid  = tid >> 5;
    const int lane = tid & 31;
    const int n0   = blockIdx.x * 16;

    for (int i = tid; i < 3 * F1C * F2C; i += 256) sW2[i] = Wc2[i];
    for (int i = tid; i < 3 * DD * F1C;  i += 256) sW1[i] = Wc1[i];
    if (tid < F1C) sb1[tid] = bc1[tid];
    if (tid < F2C) sb2[tid] = bc2[tid];
    __syncthreads();

    for (int it = 0; it < 8; it++) {
        const int item = wid * 8 + it;        // 0..63
        const int b    = item >> 4;
        const int nloc = item & 15;
        const int n    = n0 + nloc;

        if (lane < TT * DD) {
            int t = lane >> 2, d = lane & 3;
            sx[wid][lane] = ts[((b * TT + t) * NN + n) * DD + d];
        }
        __syncwarp();

        // h[p][c] = relu(bc1 + conv1), p = 0..2, c = lane
        #pragma unroll
        for (int p = 0; p < 3; p++) {
            float s = sb1[lane];
            #pragma unroll
            for (int r = 0; r < 3; r++)
                #pragma unroll
                for (int d = 0; d < DD; d++)
                    s += sx[wid][(p + r) * DD + d] * sW1[(r * DD + d) * F1C + lane];
            sh[wid][p * 32 + lane] = fmaxf(s, 0.f);
        }
        __syncwarp();

        // cond[f] = bc2 + conv2
        #pragma unroll
        for (int u = 0; u < 2; u++) {
            const int f = lane + u * 32;
            float s = sb2[f];
            #pragma unroll
            for (int p = 0; p < 3; p++)
                for (int c = 0; c < F1C; c++)
                    s += sh[wid][p * 32 + c] * sW2[(p * F1C + c) * F2C + f];
            const int cc = b * F2C + f;
            g_cond[n * CF + cc] = s;
            scT[cc][nloc] = __float2bfloat16(s);
        }
        __syncwarp();
    }
    __syncthreads();

    // coalesced condT store: 256 rows x 32 bytes
    for (int i = tid; i < CF * 2; i += 256) {
        const int row = i >> 1, half = i & 1;
        *(int4*)((char*)(g_condT + (size_t)row * NN + n0) + half * 16) =
            *(int4*)((char*)&scT[row][0] + half * 16);
    }
}

// ---------------------------------------------------------------------------
// Kernel 2: alive[k] = any(edges[:,k] != 0)
// ---------------------------------------------------------------------------
__global__ __launch_bounds__(256) void alive_kernel(const int* __restrict__ edges)
{
    const int k = blockIdx.x * blockDim.x + threadIdx.x;
    if (k >= NN) return;
    float a = 0.f;
    for (int j = 0; j < NN; j++) {
        if (edges[j * NN + k] != 0) { a = 1.f; break; }
    }
    g_alive[k] = a;
}

// ---------------------------------------------------------------------------
// Kernel 3: fused S = A @ cond (bf16 mma.sync) + row-degree + epilogue.
// grid (2, 64) x 512 threads. CTA: 64 rows x 128 cols (= 2 batches).
// 3-stage cp.async pipeline for B (condT), register-staged edges -> bf16 A.
// Epilogue: per-warp GEMV chain on the CTA's own S tile.
// ---------------------------------------------------------------------------
__global__ __launch_bounds__(512, 1) void gemm_kernel(
    const int*   __restrict__ edges,
    const float* __restrict__ ts,
    const float* __restrict__ Wg1, const float* __restrict__ bg,
    const float* __restrict__ Wd,  const float* __restrict__ bd,
    const float* __restrict__ Wo,  const float* __restrict__ bo,
    float* __restrict__ out)
{
    extern __shared__ char smem[];
    char* B0 = smem;
    char* B1 = smem + BTILE;
    char* B2 = smem + 2 * BTILE;
    char* A0 = smem + 3 * BTILE;
    char* A1 = smem + 3 * BTILE + ATILE;
    char* Bbuf[3] = {B0, B1, B2};
    char* Abuf[2] = {A0, A1};

    const int tid  = threadIdx.x;
    const int wid  = tid >> 5;
    const int lane = tid & 31;
    const int g    = lane >> 2;
    const int t    = lane & 3;
    const int mi   = wid >> 2;       // 0..3 -> 16-row block
    const int nq   = wid & 3;        // 0..3 -> 32-col block
    const int c0   = blockIdx.x * NT;     // 0 or 128
    const int j0   = blockIdx.y * MT;
    const int arow  = tid >> 3;           // 0..63 (fixed row per thread)
    const int akoff = (tid & 7) * 8;      // k-element offset within tile

    float acc[4][4] = {};
    int degacc = 0;

    // ---- prologue ----
    // B tile 0 and 1
    #pragma unroll 1
    for (int s = 0; s < 2; s++) {
        for (int ch = tid; ch < NT * 8; ch += 512) {
            int row = ch >> 3, off = ch & 7;
            cp_async16(Bbuf[s] + row * LDSB + off * 16,
                       g_condT + (size_t)(c0 + row) * NN + s * KT + off * 8);
        }
        cp_async_commit();
    }
    // A tile 0
    {
        const int4* ep = (const int4*)(edges + (size_t)(j0 + arow) * NN + akoff);
        int4 e0 = ep[0], e1 = ep[1];
        degacc += e0.x + e0.y + e0.z + e0.w + e1.x + e1.y + e1.z + e1.w;
        uint32_t w0 = (e0.x ? 0x3F80u : 0u) | ((e0.y ? 0x3F80u : 0u) << 16);
        uint32_t w1 = (e0.z ? 0x3F80u : 0u) | ((e0.w ? 0x3F80u : 0u) << 16);
        uint32_t w2 = (e1.x ? 0x3F80u : 0u) | ((e1.y ? 0x3F80u : 0u) << 16);
        uint32_t w3 = (e1.z ? 0x3F80u : 0u) | ((e1.w ? 0x3F80u : 0u) << 16);
        *(uint4*)(A0 + arow * LDSB + (tid & 7) * 16) = make_uint4(w0, w1, w2, w3);
    }
    cp_async_wait<1>();   // B0 ready
    __syncthreads();

    // ---- mainloop ----
    #pragma unroll 1
    for (int kt = 0; kt < NKT; kt++) {
        char* Acur = Abuf[kt & 1];
        char* Bcur = Bbuf[kt % 3];
        const bool pf = (kt + 1 < NKT);
        const bool pb = (kt + 2 < NKT);

        int4 e0, e1;
        if (pf) {
            const int4* ep = (const int4*)(edges + (size_t)(j0 + arow) * NN
                                           + (kt + 1) * KT + akoff);
            e0 = ep[0]; e1 = ep[1];
        }
        if (pb) {
            char* Bn = Bbuf[(kt + 2) % 3];
            const int kp = (kt + 2) * KT;
            for (int ch = tid; ch < NT * 8; ch += 512) {
                int row = ch >> 3, off = ch & 7;
                cp_async16(Bn + row * LDSB + off * 16,
                           g_condT + (size_t)(c0 + row) * NN + kp + off * 8);
            }
            cp_async_commit();
        }

        #pragma unroll
        for (int kk = 0; kk < 4; kk++) {
            const int kb = kk * 32 + t * 4;
            const char* Ab = Acur + (mi * 16 + g) * LDSB + kb;
            uint32_t a0 = *(const uint32_t*)(Ab);
            uint32_t a1 = *(const uint32_t*)(Ab + 8 * LDSB);
            uint32_t a2 = *(const uint32_t*)(Ab + 16);
            uint32_t a3 = *(const uint32_t*)(Ab + 8 * LDSB + 16);
            #pragma unroll
            for (int ni = 0; ni < 4; ni++) {
                const char* Bb = Bcur + (nq * 32 + ni * 8 + g) * LDSB + kb;
                mma_bf16(acc[ni], a0, a1, a2, a3,
                         *(const uint32_t*)Bb, *(const uint32_t*)(Bb + 16));
            }
        }

        if (pf) {
            degacc += e0.x + e0.y + e0.z + e0.w + e1.x + e1.y + e1.z + e1.w;
            uint32_t w0 = (e0.x ? 0x3F80u : 0u) | ((e0.y ? 0x3F80u : 0u) << 16);
            uint32_t w1 = (e0.z ? 0x3F80u : 0u) | ((e0.w ? 0x3F80u : 0u) << 16);
            uint32_t w2 = (e1.x ? 0x3F80u : 0u) | ((e1.y ? 0x3F80u : 0u) << 16);
            uint32_t w3 = (e1.z ? 0x3F80u : 0u) | ((e1.w ? 0x3F80u : 0u) << 16);
            *(uint4*)(Abuf[(kt + 1) & 1] + arow * LDSB + (tid & 7) * 16) =
                make_uint4(w0, w1, w2, w3);
        }
        if (pb) cp_async_wait<1>(); else cp_async_wait<0>();
        __syncthreads();
    }

    // ---- epilogue overlay ----
    float* sf   = (float*)smem;
    float* sS   = sf;               // 8192  (64 x 128)
    float* sWg1 = sf + 8192;        // 4096
    float* sWd  = sf + 12288;       // 8192
    float* sWo  = sf + 20480;       // 256
    float* sbg  = sf + 20736;       // 64
    float* sbd  = sf + 20800;       // 64
    float* sbo  = sf + 20864;       // 64 (4 used)
    float* sinv = sf + 20928;       // 64
    float* swk  = sf + 20992;       // 16 warps x 256

    // row degree: reduce over the 8 staging lanes per row (within-warp)
    int d8 = degacc;
    d8 += __shfl_xor_sync(0xffffffffu, d8, 1);
    d8 += __shfl_xor_sync(0xffffffffu, d8, 2);
    d8 += __shfl_xor_sync(0xffffffffu, d8, 4);
    if ((tid & 7) == 0) sinv[arow] = 1.0f / fmaxf((float)d8, 1.0f);

    // spill S to smem
    #pragma unroll
    for (int ni = 0; ni < 4; ni++) {
        const int row = mi * 16 + g;
        const int col = nq * 32 + ni * 8 + 2 * t;
        sS[row * 128 + col]           = acc[ni][0];
        sS[row * 128 + col + 1]       = acc[ni][1];
        sS[(row + 8) * 128 + col]     = acc[ni][2];
        sS[(row + 8) * 128 + col + 1] = acc[ni][3];
    }
    // weights
    for (int i = tid; i < 4096; i += 512) sWg1[i] = Wg1[i];
    for (int i = tid; i < 8192; i += 512) sWd[i]  = Wd[i];
    if (tid < 256) sWo[tid] = Wo[tid];
    if (tid < 64) { sbg[tid] = bg[tid]; sbd[tid] = bd[tid]; }
    if (tid < 4)  sbo[tid] = bo[tid];
    __syncthreads();

    // per-warp GEMV chain: 128 tasks (64 rows x 2 local batches), 8 per warp
    float* agg = swk + wid * 256;
    float* cnd = agg + 64;
    float* Gv  = agg + 128;
    float* Hv  = agg + 192;

    for (int it = 0; it < 8; it++) {
        const int tloc = wid * 8 + it;
        const int jl = tloc >> 1, bl = tloc & 1;
        const int j  = j0 + jl;
        const int b  = blockIdx.x * 2 + bl;
        const float invd = sinv[jl];
        float e = 0.f, al = 0.f;
        if (lane == 0) {
            e  = (float)edges[(size_t)j * NN + j];
            al = g_alive[j];
        }
        e  = __shfl_sync(0xffffffffu, e, 0);
        al = __shfl_sync(0xffffffffu, al, 0);

        #pragma unroll
        for (int u = 0; u < 2; u++) {
            const int i = lane + u * 32;
            const float cv = g_cond[(size_t)j * CF + c0 + bl * 64 + i];
            const float sv = sS[jl * 128 + bl * 64 + i];
            cnd[i] = cv;
            agg[i] = (sv - e * cv) * invd;
        }
        __syncwarp();

        #pragma unroll
        for (int u = 0; u < 2; u++) {
            const int f = lane + u * 32;
            float gv = sbg[f];
            #pragma unroll
            for (int i = 0; i < 64; i++) gv += agg[i] * sWg1[i * 64 + f];
            Gv[f] = tanhf(gv) * al;
        }
        __syncwarp();

        #pragma unroll
        for (int u = 0; u < 2; u++) {
            const int f = lane + u * 32;
            float h = sbd[f];
            #pragma unroll
            for (int i = 0; i < 64; i++) h += cnd[i] * sWd[i * 64 + f];
            #pragma unroll
            for (int i = 0; i < 64; i++) h += Gv[i] * sWd[(64 + i) * 64 + f];
            Hv[f] = fmaxf(h, 0.f);
        }
        __syncwarp();

        if (lane < 4) {
            const int d = lane;
            float o = sbo[d];
            #pragma unroll
            for (int i = 0; i < 64; i++) o += Hv[i] * sWo[i * DD + d];
            const float last = ts[((size_t)(b * TT + 4) * NN + j) * DD + d];
            out[((size_t)b * NN + j) * DD + d] = last + tanhf(o);
        }
        __syncwarp();
    }
}

// ---------------------------------------------------------------------------
// Inputs (metadata order): time_segs, edges, Wc1, bc1, Wc2, bc2,
//                          Wg1, bg, Wd, bd, Wo, bo
// ---------------------------------------------------------------------------
extern "C" void kernel_launch(void* const* d_in, const int* in_sizes, int n_in,
                              void* d_out, int out_size)
{
    const float* ts   = (const float*)d_in[0];
    const int*   edges= (const int*)  d_in[1];
    const float* Wc1  = (const float*)d_in[2];
    const float* bc1  = (const float*)d_in[3];
    const float* Wc2  = (const float*)d_in[4];
    const float* bc2  = (const float*)d_in[5];
    const float* Wg1  = (const float*)d_in[6];
    const float* bg   = (const float*)d_in[7];
    const float* Wd   = (const float*)d_in[8];
    const float* bd   = (const float*)d_in[9];
    const float* Wo   = (const float*)d_in[10];
    const float* bo   = (const float*)d_in[11];
    float* out = (float*)d_out;

    static bool attr_done = false;
    if (!attr_done) {
        cudaFuncSetAttribute(gemm_kernel,
                             cudaFuncAttributeMaxDynamicSharedMemorySize, GEMM_SMEM);
        attr_done = true;
    }

    cond_kernel <<<NN / 16, 256>>>(ts, Wc1, bc1, Wc2, bc2);
    alive_kernel<<<NN / 256, 256>>>(edges);
    gemm_kernel <<<dim3(2, NN / MT), 512, GEMM_SMEM>>>(edges, ts, Wg1, bg,
                                                       Wd, bd, Wo, bo, out);
}